// round 1
// baseline (speedup 1.0000x reference)
#include <cuda_runtime.h>
#include <math.h>

#define NR  8192
#define DIM 512
#define BM  128
#define BN  128
#define BK  16

// Scratch (allocation-free rule: __device__ globals)
__device__ float    g_xn[NR * DIM];
__device__ float    g_yn[NR * DIM];
__device__ unsigned g_rmax[NR];
__device__ unsigned g_cmax[NR];

// Order-preserving float <-> uint mapping (monotone under unsigned compare)
__device__ __forceinline__ unsigned f2o(float f) {
    unsigned b = __float_as_uint(f);
    return (b & 0x80000000u) ? ~b : (b | 0x80000000u);
}
__device__ __forceinline__ float o2f(unsigned o) {
    return __uint_as_float((o & 0x80000000u) ? (o ^ 0x80000000u) : ~o);
}

__global__ void init_kernel(float* out, int out_size) {
    int i = blockIdx.x * blockDim.x + threadIdx.x;
    if (i < NR) { g_rmax[i] = 0u; g_cmax[i] = 0u; }  // key 0 == -NaN sentinel (below any real)
    if (i < out_size) out[i] = 0.f;
}

// One block (128 threads) per row; blockIdx.y selects ex/ey.
__global__ void normalize_kernel(const float* __restrict__ ex,
                                 const float* __restrict__ ey) {
    const float* src = blockIdx.y ? ey : ex;
    float*       dst = blockIdx.y ? g_yn : g_xn;
    int row = blockIdx.x;
    int t   = threadIdx.x;  // 128 threads, one float4 each (512 elems)
    float4 v = ((const float4*)(src + (size_t)row * DIM))[t];
    float ss = v.x * v.x + v.y * v.y + v.z * v.z + v.w * v.w;
#pragma unroll
    for (int off = 16; off; off >>= 1) ss += __shfl_xor_sync(0xffffffffu, ss, off);
    __shared__ float sred[4];
    if ((t & 31) == 0) sred[t >> 5] = ss;
    __syncthreads();
    float tot  = sred[0] + sred[1] + sred[2] + sred[3];
    float inv  = 1.0f / fmaxf(sqrtf(tot), 1e-8f);
    v.x *= inv; v.y *= inv; v.z *= inv; v.w *= inv;
    ((float4*)(dst + (size_t)row * DIM))[t] = v;
}

// Fused GEMM + row/col max. C[m,n] = dot(xn[m], yn[n]); never materialized.
// 128x128 tile per CTA, BK=16, double-buffered smem, 8x8 register micro-tile.
__global__ __launch_bounds__(256, 2) void gemm_max_kernel() {
    __shared__ float As[2][BK][BM];
    __shared__ float Bs[2][BK][BN];
    __shared__ unsigned sR[BM];
    __shared__ unsigned sC[BN];

    const int tid = threadIdx.x;
    const int tx  = tid & 15;       // 0..15 -> col group
    const int ty  = tid >> 4;       // 0..15 -> row group
    const int cm  = blockIdx.y * BM;
    const int cn  = blockIdx.x * BN;

    const int lrow0 = tid >> 2;     // 0..63 (two phases -> 0..127)
    const int lc4   = tid & 3;      // which float4 within the 16-wide k slab

    float acc[8][8];
#pragma unroll
    for (int i = 0; i < 8; i++)
#pragma unroll
        for (int j = 0; j < 8; j++) acc[i][j] = 0.f;

    float4 ra[2], rb[2];

    // prologue: load k-tile 0
#pragma unroll
    for (int p = 0; p < 2; p++) {
        int row = lrow0 + p * 64;
        ra[p] = *(const float4*)&g_xn[(size_t)(cm + row) * DIM + lc4 * 4];
        rb[p] = *(const float4*)&g_yn[(size_t)(cn + row) * DIM + lc4 * 4];
    }
#pragma unroll
    for (int p = 0; p < 2; p++) {
        int row = lrow0 + p * 64;
        As[0][lc4 * 4 + 0][row] = ra[p].x; As[0][lc4 * 4 + 1][row] = ra[p].y;
        As[0][lc4 * 4 + 2][row] = ra[p].z; As[0][lc4 * 4 + 3][row] = ra[p].w;
        Bs[0][lc4 * 4 + 0][row] = rb[p].x; Bs[0][lc4 * 4 + 1][row] = rb[p].y;
        Bs[0][lc4 * 4 + 2][row] = rb[p].z; Bs[0][lc4 * 4 + 3][row] = rb[p].w;
    }
    __syncthreads();

    const int NK = DIM / BK;  // 32
    for (int kt = 0; kt < NK; kt++) {
        int buf = kt & 1;
        if (kt + 1 < NK) {
            int k0 = (kt + 1) * BK;
#pragma unroll
            for (int p = 0; p < 2; p++) {
                int row = lrow0 + p * 64;
                ra[p] = *(const float4*)&g_xn[(size_t)(cm + row) * DIM + k0 + lc4 * 4];
                rb[p] = *(const float4*)&g_yn[(size_t)(cn + row) * DIM + k0 + lc4 * 4];
            }
        }
#pragma unroll
        for (int kk = 0; kk < BK; kk++) {
            float a[8], b[8];
            *(float4*)&a[0] = *(const float4*)&As[buf][kk][ty * 8];
            *(float4*)&a[4] = *(const float4*)&As[buf][kk][ty * 8 + 4];
            *(float4*)&b[0] = *(const float4*)&Bs[buf][kk][tx * 8];
            *(float4*)&b[4] = *(const float4*)&Bs[buf][kk][tx * 8 + 4];
#pragma unroll
            for (int i = 0; i < 8; i++)
#pragma unroll
                for (int j = 0; j < 8; j++)
                    acc[i][j] = fmaf(a[i], b[j], acc[i][j]);
        }
        if (kt + 1 < NK) {
            int nb = buf ^ 1;
#pragma unroll
            for (int p = 0; p < 2; p++) {
                int row = lrow0 + p * 64;
                As[nb][lc4 * 4 + 0][row] = ra[p].x; As[nb][lc4 * 4 + 1][row] = ra[p].y;
                As[nb][lc4 * 4 + 2][row] = ra[p].z; As[nb][lc4 * 4 + 3][row] = ra[p].w;
                Bs[nb][lc4 * 4 + 0][row] = rb[p].x; Bs[nb][lc4 * 4 + 1][row] = rb[p].y;
                Bs[nb][lc4 * 4 + 2][row] = rb[p].z; Bs[nb][lc4 * 4 + 3][row] = rb[p].w;
            }
            __syncthreads();
        }
    }

    // Fused epilogue: tile-local row/col max -> shared atomics -> global atomics
    if (tid < BM) { sR[tid] = 0u; sC[tid] = 0u; }
    __syncthreads();
#pragma unroll
    for (int i = 0; i < 8; i++) {
        float rm = acc[i][0];
#pragma unroll
        for (int j = 1; j < 8; j++) rm = fmaxf(rm, acc[i][j]);
        atomicMax(&sR[ty * 8 + i], f2o(rm));
    }
#pragma unroll
    for (int j = 0; j < 8; j++) {
        float cmx = acc[0][j];
#pragma unroll
        for (int i = 1; i < 8; i++) cmx = fmaxf(cmx, acc[i][j]);
        atomicMax(&sC[tx * 8 + j], f2o(cmx));
    }
    __syncthreads();
    if (tid < BM) {
        atomicMax(&g_rmax[cm + tid], sR[tid]);
        atomicMax(&g_cmax[cn + tid], sC[tid]);
    }
}

// lp = -0.5*((x-1)/0.3)^2 - log(0.3) - 0.5*log(2*pi);  out = sum(-exp(lp)*lp)
__global__ void entropy_kernel(float* __restrict__ out) {
    const unsigned* src = blockIdx.x ? g_cmax : g_rmax;
    int t = threadIdx.x;  // 1024
    float sum = 0.f;
    for (int i = t; i < NR; i += 1024) {
        float x  = o2f(src[i]);
        float z  = (x - 1.0f) * (1.0f / 0.3f);
        float lp = fmaf(-0.5f, z * z, 0.28503427112126339f);  // -log(0.3)-0.5*log(2pi)
        sum -= expf(lp) * lp;
    }
#pragma unroll
    for (int off = 16; off; off >>= 1) sum += __shfl_xor_sync(0xffffffffu, sum, off);
    __shared__ float s[32];
    if ((t & 31) == 0) s[t >> 5] = sum;
    __syncthreads();
    if (t < 32) {
        float v = s[t];
#pragma unroll
        for (int off = 16; off; off >>= 1) v += __shfl_xor_sync(0xffffffffu, v, off);
        if (t == 0) out[blockIdx.x] = v;
    }
}

extern "C" void kernel_launch(void* const* d_in, const int* in_sizes, int n_in,
                              void* d_out, int out_size) {
    const float* ex = (const float*)d_in[0];
    const float* ey = (const float*)d_in[1];
    float* out = (float*)d_out;

    init_kernel<<<(NR + 255) / 256, 256>>>(out, out_size);
    normalize_kernel<<<dim3(NR, 2), 128>>>(ex, ey);
    gemm_max_kernel<<<dim3(NR / BN, NR / BM), 256>>>();
    entropy_kernel<<<2, 1024>>>(out);
}

// round 3
// speedup vs baseline: 5.5872x; 5.5872x over previous
#include <cuda_runtime.h>
#include <cuda_bf16.h>
#include <math.h>
#include <stdint.h>

#define NR  8192
#define DIM 512
#define TM  128
#define TN  256
#define KC  64
#define NCHUNK (DIM / KC)          // 8
#define NTHREADS 512
#define STAGE_BYTES 49152          // A 16KB + B 32KB
#define SMEM_RED (4 * STAGE_BYTES) // 196608
#define SMEM_TOTAL (SMEM_RED + 384 * 8)

// ---------------- device scratch (allocation-free rule) ----------------
__device__ float              g_xn[NR * DIM];
__device__ float              g_yn[NR * DIM];
__device__ __nv_bfloat16      g_xh[NR * DIM];
__device__ __nv_bfloat16      g_yh[NR * DIM];
__device__ unsigned long long g_rbest[NR];   // (f2o(val)<<32) | argmax col
__device__ unsigned long long g_cbest[NR];   // (f2o(val)<<32) | argmax row
__device__ float              g_maxv[2 * NR];

__device__ __forceinline__ unsigned f2o(float f) {
    unsigned b = __float_as_uint(f);
    return (b & 0x80000000u) ? ~b : (b | 0x80000000u);
}
__device__ __forceinline__ unsigned long long umax64(unsigned long long a,
                                                     unsigned long long b) {
    return a > b ? a : b;
}

// ---------------- PTX helpers (sm_80-era, valid on sm_100 base) ----------------
__device__ __forceinline__ uint32_t smem_u32(const void* p) {
    uint32_t a;
    asm("{ .reg .u64 t; cvta.to.shared.u64 t, %1; cvt.u32.u64 %0, t; }" : "=r"(a) : "l"(p));
    return a;
}
__device__ __forceinline__ void cp16(uint32_t dst, const void* src) {
    asm volatile("cp.async.cg.shared.global [%0], [%1], 16;" :: "r"(dst), "l"(src));
}
__device__ __forceinline__ void cp_commit() { asm volatile("cp.async.commit_group;"); }
template <int N> __device__ __forceinline__ void cp_wait() {
    asm volatile("cp.async.wait_group %0;" :: "n"(N));
}
__device__ __forceinline__ void ldsm4(uint32_t& r0, uint32_t& r1, uint32_t& r2,
                                      uint32_t& r3, uint32_t addr) {
    asm volatile("ldmatrix.sync.aligned.m8n8.x4.shared.b16 {%0,%1,%2,%3}, [%4];"
                 : "=r"(r0), "=r"(r1), "=r"(r2), "=r"(r3) : "r"(addr));
}
__device__ __forceinline__ void mma16816(float* c, const uint32_t* a, const uint32_t* b) {
    asm volatile(
        "mma.sync.aligned.m16n8k16.row.col.f32.bf16.bf16.f32 "
        "{%0,%1,%2,%3}, {%4,%5,%6,%7}, {%8,%9}, {%0,%1,%2,%3};"
        : "+f"(c[0]), "+f"(c[1]), "+f"(c[2]), "+f"(c[3])
        : "r"(a[0]), "r"(a[1]), "r"(a[2]), "r"(a[3]), "r"(b[0]), "r"(b[1]));
}

// ---------------- kernels ----------------
__global__ void init_kernel(float* out, int out_size) {
    int i = blockIdx.x * blockDim.x + threadIdx.x;
    if (i < NR) { g_rbest[i] = 0ull; g_cbest[i] = 0ull; }
    if (i < out_size) out[i] = 0.f;
}

// one 128-thread block per row; y: 0 -> ex, 1 -> ey. fp32 + bf16 outputs.
__global__ void normalize_kernel(const float* __restrict__ ex,
                                 const float* __restrict__ ey) {
    const float* src = blockIdx.y ? ey : ex;
    float*       dst = blockIdx.y ? g_yn : g_xn;
    __nv_bfloat16* dh = blockIdx.y ? g_yh : g_xh;
    int row = blockIdx.x, t = threadIdx.x;
    float4 v = ((const float4*)(src + (size_t)row * DIM))[t];
    float ss = v.x * v.x + v.y * v.y + v.z * v.z + v.w * v.w;
#pragma unroll
    for (int off = 16; off; off >>= 1) ss += __shfl_xor_sync(0xffffffffu, ss, off);
    __shared__ float sred[4];
    if ((t & 31) == 0) sred[t >> 5] = ss;
    __syncthreads();
    float inv = 1.0f / fmaxf(sqrtf(sred[0] + sred[1] + sred[2] + sred[3]), 1e-8f);
    v.x *= inv; v.y *= inv; v.z *= inv; v.w *= inv;
    ((float4*)(dst + (size_t)row * DIM))[t] = v;
    __nv_bfloat162 p0 = {__float2bfloat16_rn(v.x), __float2bfloat16_rn(v.y)};
    __nv_bfloat162 p1 = {__float2bfloat16_rn(v.z), __float2bfloat16_rn(v.w)};
    ((__nv_bfloat162*)(dh + (size_t)row * DIM))[t * 2]     = p0;
    ((__nv_bfloat162*)(dh + (size_t)row * DIM))[t * 2 + 1] = p1;
}

// load one K-chunk (64 bf16 = 128B rows, SW128 swizzle): A 128 rows, B 256 rows
__device__ __forceinline__ void load_chunk(int chunk, int slot, int cm, int cn,
                                           uint32_t sbase) {
    const int k0 = chunk * KC;
    const uint32_t s0 = sbase + slot * STAGE_BYTES;
    const int tid = threadIdx.x;
#pragma unroll
    for (int i = 0; i < 2; i++) {        // A: 1024 segs
        int c = tid + i * NTHREADS;
        int row = c >> 3, seg = c & 7;
        uint32_t off = row * 128 + seg * 16;
        off ^= ((off >> 3) & 0x70);
        cp16(s0 + off, g_xh + (size_t)(cm + row) * DIM + k0 + seg * 8);
    }
#pragma unroll
    for (int i = 0; i < 4; i++) {        // B: 2048 segs
        int c = tid + i * NTHREADS;
        int row = c >> 3, seg = c & 7;
        uint32_t off = row * 128 + seg * 16;
        off ^= ((off >> 3) & 0x70);
        cp16(s0 + 16384 + off, g_yh + (size_t)(cn + row) * DIM + k0 + seg * 8);
    }
}

__global__ __launch_bounds__(NTHREADS, 1) void gemm_max_kernel() {
    extern __shared__ char smem[];
    const uint32_t sbase = smem_u32(smem);
    const int tid = threadIdx.x, wid = tid >> 5, lane = tid & 31;
    const int wm = wid >> 2, wn = wid & 3;          // 4x4 warps, warp tile 32x64
    const int cm = blockIdx.y * TM, cn = blockIdx.x * TN;
    unsigned long long* sRow = (unsigned long long*)(smem + SMEM_RED);  // 128
    unsigned long long* sCol = sRow + 128;                              // 256

    for (int i = tid; i < 384; i += NTHREADS) sRow[i] = 0ull;

    float acc[2][8][4];
#pragma unroll
    for (int mi = 0; mi < 2; mi++)
#pragma unroll
        for (int nj = 0; nj < 8; nj++)
#pragma unroll
            for (int p = 0; p < 4; p++) acc[mi][nj][p] = 0.f;

    // ldmatrix address components (group-of-8 pattern)
    const int g = lane >> 3;
    const int a_row = wm * 32 + (lane & 7) + (g & 1) * 8;  // + mi*16
    const int a_sel = g >> 1;                              // seg = ks*2 + sel
    const int b_row = wn * 64 + (lane & 7) + (g >> 1) * 8; // + nq*16
    const int b_sel = g & 1;

    // prologue: chunks 0..2 into slots 0..2
    for (int c = 0; c < 3; c++) { load_chunk(c, c, cm, cn, sbase); cp_commit(); }

    for (int kc = 0; kc < NCHUNK; kc++) {
        __syncthreads();   // all warps done with chunk kc-1 (slot being overwritten)
        if (kc + 3 < NCHUNK) { load_chunk(kc + 3, (kc + 3) & 3, cm, cn, sbase); cp_commit(); }
        if (kc < 5)      cp_wait<3>();
        else if (kc == 5) cp_wait<2>();
        else if (kc == 6) cp_wait<1>();
        else              cp_wait<0>();
        __syncthreads();

        const uint32_t As = sbase + (kc & 3) * STAGE_BYTES;
        const uint32_t Bs = As + 16384;
#pragma unroll
        for (int ks = 0; ks < 4; ks++) {
            uint32_t a[2][4];
#pragma unroll
            for (int mi = 0; mi < 2; mi++) {
                uint32_t off = (a_row + mi * 16) * 128 + (ks * 2 + a_sel) * 16;
                off ^= ((off >> 3) & 0x70);
                ldsm4(a[mi][0], a[mi][1], a[mi][2], a[mi][3], As + off);
            }
            uint32_t b[8][2];
#pragma unroll
            for (int nq = 0; nq < 4; nq++) {
                uint32_t off = (b_row + nq * 16) * 128 + (ks * 2 + b_sel) * 16;
                off ^= ((off >> 3) & 0x70);
                ldsm4(b[nq * 2][0], b[nq * 2][1], b[nq * 2 + 1][0], b[nq * 2 + 1][1],
                      Bs + off);
            }
#pragma unroll
            for (int mi = 0; mi < 2; mi++)
#pragma unroll
                for (int nj = 0; nj < 8; nj++)
                    mma16816(acc[mi][nj], a[mi], b[nj]);
        }
    }

    // -------- epilogue: row/col argmax from register fragments --------
    // fragment: c0,c1 at row lane>>2 cols +0,+1; c2,c3 at row+8
#pragma unroll
    for (int mi = 0; mi < 2; mi++)
#pragma unroll
        for (int h = 0; h < 2; h++) {
            unsigned long long best = 0ull;
#pragma unroll
            for (int nj = 0; nj < 8; nj++)
#pragma unroll
                for (int p = 0; p < 2; p++) {
                    float v = acc[mi][nj][h * 2 + p];
                    unsigned col = cn + wn * 64 + nj * 8 + (lane & 3) * 2 + p;
                    best = umax64(best, ((unsigned long long)f2o(v) << 32) | col);
                }
            best = umax64(best, __shfl_xor_sync(0xffffffffu, best, 1));
            best = umax64(best, __shfl_xor_sync(0xffffffffu, best, 2));
            if ((lane & 3) == 0)
                atomicMax(&sRow[wm * 32 + mi * 16 + h * 8 + (lane >> 2)], best);
        }
#pragma unroll
    for (int nj = 0; nj < 8; nj++)
#pragma unroll
        for (int p = 0; p < 2; p++) {
            unsigned long long best = 0ull;
#pragma unroll
            for (int mi = 0; mi < 2; mi++)
#pragma unroll
                for (int h = 0; h < 2; h++) {
                    float v = acc[mi][nj][h * 2 + p];
                    unsigned row = cm + wm * 32 + mi * 16 + h * 8 + (lane >> 2);
                    best = umax64(best, ((unsigned long long)f2o(v) << 32) | row);
                }
            best = umax64(best, __shfl_xor_sync(0xffffffffu, best, 4));
            best = umax64(best, __shfl_xor_sync(0xffffffffu, best, 8));
            best = umax64(best, __shfl_xor_sync(0xffffffffu, best, 16));
            if (lane < 4)
                atomicMax(&sCol[wn * 64 + nj * 8 + (lane & 3) * 2 + p], best);
        }
    __syncthreads();
    if (tid < 128) atomicMax(&g_rbest[cm + tid], sRow[tid]);
    if (tid < 256) atomicMax(&g_cbest[cn + tid], sCol[tid]);
}

// one warp per (row|col): recompute winning dot product in exact fp32
__global__ void refine_kernel() {
    int w    = (blockIdx.x * blockDim.x + threadIdx.x) >> 5;
    int lane = threadIdx.x & 31;
    if (w >= 2 * NR) return;
    const float *va, *vb;
    if (w < NR) {
        unsigned m = (unsigned)g_rbest[w];
        va = g_xn + (size_t)w * DIM;  vb = g_yn + (size_t)m * DIM;
    } else {
        int c = w - NR;
        unsigned m = (unsigned)g_cbest[c];
        va = g_xn + (size_t)m * DIM;  vb = g_yn + (size_t)c * DIM;
    }
    float s = 0.f;
#pragma unroll
    for (int i = 0; i < 4; i++) {
        int e = (i * 32 + lane) * 4;
        float4 a = *(const float4*)(va + e);
        float4 b = *(const float4*)(vb + e);
        s += a.x * b.x + a.y * b.y + a.z * b.z + a.w * b.w;
    }
#pragma unroll
    for (int off = 16; off; off >>= 1) s += __shfl_xor_sync(0xffffffffu, s, off);
    if (lane == 0) g_maxv[w] = s;
}

// lp = -0.5*((x-1)/0.3)^2 - log(0.3) - 0.5*log(2pi); out[side] += -exp(lp)*lp
__global__ void entropy_kernel(float* __restrict__ out) {
    int side = blockIdx.y;
    int i = blockIdx.x * blockDim.x + threadIdx.x;   // 8 x 1024 = 8192
    float x  = g_maxv[side * NR + i];
    float z  = (x - 1.0f) * (1.0f / 0.3f);
    float lp = fmaf(-0.5f, z * z, 0.28503427112126339f);
    float sum = -expf(lp) * lp;
#pragma unroll
    for (int off = 16; off; off >>= 1) sum += __shfl_xor_sync(0xffffffffu, sum, off);
    __shared__ float s[32];
    int t = threadIdx.x;
    if ((t & 31) == 0) s[t >> 5] = sum;
    __syncthreads();
    if (t < 32) {
        float v = s[t];
#pragma unroll
        for (int off = 16; off; off >>= 1) v += __shfl_xor_sync(0xffffffffu, v, off);
        if (t == 0) atomicAdd(&out[side], v);
    }
}

extern "C" void kernel_launch(void* const* d_in, const int* in_sizes, int n_in,
                              void* d_out, int out_size) {
    const float* ex = (const float*)d_in[0];
    const float* ey = (const float*)d_in[1];
    float* out = (float*)d_out;

    cudaFuncSetAttribute(gemm_max_kernel, cudaFuncAttributeMaxDynamicSharedMemorySize,
                         SMEM_TOTAL);

    init_kernel<<<(NR + 255) / 256, 256>>>(out, out_size);
    normalize_kernel<<<dim3(NR, 2), 128>>>(ex, ey);
    gemm_max_kernel<<<dim3(NR / TN, NR / TM), NTHREADS, SMEM_TOTAL>>>();
    refine_kernel<<<(2 * NR * 32) / 256, 256>>>();
    entropy_kernel<<<dim3(8, 2), 1024>>>(out);
}

// round 4
// speedup vs baseline: 6.3767x; 1.1413x over previous
#include <cuda_runtime.h>
#include <cuda_bf16.h>
#include <math.h>
#include <stdint.h>

#define NR  8192
#define DIM 512
#define TM  128
#define TN  128
#define KC  64
#define NCHUNK (DIM / KC)            // 8
#define NTHREADS 256
#define STAGE_BYTES 32768            // A 16KB + B 16KB
#define NSTAGE 3
#define SMEM_RED (NSTAGE * STAGE_BYTES)      // 98304
#define SMEM_TOTAL (SMEM_RED + 256 * 8)      // + sRow(128)+sCol(128) u64

// ---------------- device scratch (allocation-free rule) ----------------
__device__ __nv_bfloat16      g_xh[NR * DIM];
__device__ __nv_bfloat16      g_yh[NR * DIM];
__device__ float              g_nrm[2 * NR];   // clamped norms: [0..NR) ex, [NR..) ey
__device__ unsigned long long g_rbest[NR];     // (f2o(val)<<32) | argmax col
__device__ unsigned long long g_cbest[NR];     // (f2o(val)<<32) | argmax row

__device__ __forceinline__ unsigned f2o(float f) {
    unsigned b = __float_as_uint(f);
    return (b & 0x80000000u) ? ~b : (b | 0x80000000u);
}
__device__ __forceinline__ unsigned long long umax64(unsigned long long a,
                                                     unsigned long long b) {
    return a > b ? a : b;
}

// ---------------- PTX helpers (sm_80-era, valid on sm_100 base) ----------------
__device__ __forceinline__ uint32_t smem_u32(const void* p) {
    uint32_t a;
    asm("{ .reg .u64 t; cvta.to.shared.u64 t, %1; cvt.u32.u64 %0, t; }" : "=r"(a) : "l"(p));
    return a;
}
__device__ __forceinline__ void cp16(uint32_t dst, const void* src) {
    asm volatile("cp.async.cg.shared.global [%0], [%1], 16;" :: "r"(dst), "l"(src));
}
__device__ __forceinline__ void cp_commit() { asm volatile("cp.async.commit_group;"); }
template <int N> __device__ __forceinline__ void cp_wait() {
    asm volatile("cp.async.wait_group %0;" :: "n"(N));
}
__device__ __forceinline__ void ldsm4(uint32_t& r0, uint32_t& r1, uint32_t& r2,
                                      uint32_t& r3, uint32_t addr) {
    asm volatile("ldmatrix.sync.aligned.m8n8.x4.shared.b16 {%0,%1,%2,%3}, [%4];"
                 : "=r"(r0), "=r"(r1), "=r"(r2), "=r"(r3) : "r"(addr));
}
__device__ __forceinline__ void mma16816(float* c, const uint32_t* a, const uint32_t* b) {
    asm volatile(
        "mma.sync.aligned.m16n8k16.row.col.f32.bf16.bf16.f32 "
        "{%0,%1,%2,%3}, {%4,%5,%6,%7}, {%8,%9}, {%0,%1,%2,%3};"
        : "+f"(c[0]), "+f"(c[1]), "+f"(c[2]), "+f"(c[3])
        : "r"(a[0]), "r"(a[1]), "r"(a[2]), "r"(a[3]), "r"(b[0]), "r"(b[1]));
}

// ---------------- kernels ----------------
__global__ void init_kernel(float* out, int out_size) {
    int i = blockIdx.x * blockDim.x + threadIdx.x;
    if (i < NR) { g_rbest[i] = 0ull; g_cbest[i] = 0ull; }
    if (i < out_size) out[i] = 0.f;
}

// one 128-thread block per row; y: 0 -> ex, 1 -> ey. bf16 normalized + norm.
__global__ void normalize_kernel(const float* __restrict__ ex,
                                 const float* __restrict__ ey) {
    const float* src  = blockIdx.y ? ey : ex;
    __nv_bfloat16* dh = blockIdx.y ? g_yh : g_xh;
    int row = blockIdx.x, t = threadIdx.x;
    float4 v = ((const float4*)(src + (size_t)row * DIM))[t];
    float ss = v.x * v.x + v.y * v.y + v.z * v.z + v.w * v.w;
#pragma unroll
    for (int off = 16; off; off >>= 1) ss += __shfl_xor_sync(0xffffffffu, ss, off);
    __shared__ float sred[4];
    if ((t & 31) == 0) sred[t >> 5] = ss;
    __syncthreads();
    float nrm = fmaxf(sqrtf(sred[0] + sred[1] + sred[2] + sred[3]), 1e-8f);
    if (t == 0) g_nrm[blockIdx.y * NR + row] = nrm;
    float inv = 1.0f / nrm;
    __nv_bfloat162 p0 = {__float2bfloat16_rn(v.x * inv), __float2bfloat16_rn(v.y * inv)};
    __nv_bfloat162 p1 = {__float2bfloat16_rn(v.z * inv), __float2bfloat16_rn(v.w * inv)};
    ((__nv_bfloat162*)(dh + (size_t)row * DIM))[t * 2]     = p0;
    ((__nv_bfloat162*)(dh + (size_t)row * DIM))[t * 2 + 1] = p1;
}

// load one K-chunk (64 bf16 = 128B rows, SW128 swizzle): A 128 rows + B 128 rows
__device__ __forceinline__ void load_chunk(int chunk, int slot, int cm, int cn,
                                           uint32_t sbase) {
    const int k0 = chunk * KC;
    const uint32_t s0 = sbase + slot * STAGE_BYTES;
    const int tid = threadIdx.x;
#pragma unroll
    for (int i = 0; i < 4; i++) {
        int c = tid + i * NTHREADS;          // 0..1023
        int row = c >> 3, seg = c & 7;
        uint32_t off = row * 128 + seg * 16;
        off ^= ((off >> 3) & 0x70);
        cp16(s0 + off, g_xh + (size_t)(cm + row) * DIM + k0 + seg * 8);
    }
#pragma unroll
    for (int i = 0; i < 4; i++) {
        int c = tid + i * NTHREADS;
        int row = c >> 3, seg = c & 7;
        uint32_t off = row * 128 + seg * 16;
        off ^= ((off >> 3) & 0x70);
        cp16(s0 + 16384 + off, g_yh + (size_t)(cn + row) * DIM + k0 + seg * 8);
    }
}

__global__ __launch_bounds__(NTHREADS, 2) void gemm_max_kernel() {
    extern __shared__ char smem[];
    const uint32_t sbase = smem_u32(smem);
    const int tid = threadIdx.x, wid = tid >> 5, lane = tid & 31;
    const int wm = wid >> 1, wn = wid & 1;           // 4x2 warps, warp tile 32x64
    const int cm = blockIdx.y * TM, cn = blockIdx.x * TN;
    unsigned long long* sRow = (unsigned long long*)(smem + SMEM_RED);  // 128
    unsigned long long* sCol = sRow + 128;                              // 128

    for (int i = tid; i < 256; i += NTHREADS) sRow[i] = 0ull;

    float acc[2][8][4];
#pragma unroll
    for (int mi = 0; mi < 2; mi++)
#pragma unroll
        for (int nj = 0; nj < 8; nj++)
#pragma unroll
            for (int p = 0; p < 4; p++) acc[mi][nj][p] = 0.f;

    // ldmatrix address components (group-of-8 pattern)
    const int g = lane >> 3;
    const int a_row = wm * 32 + (lane & 7) + (g & 1) * 8;   // + mi*16
    const int a_sel = g >> 1;                               // seg = ks*2 + sel
    const int b_row = wn * 64 + (lane & 7) + (g >> 1) * 8;  // + nq*16
    const int b_sel = g & 1;

    // prologue: chunks 0,1 into slots 0,1
    load_chunk(0, 0, cm, cn, sbase); cp_commit();
    load_chunk(1, 1, cm, cn, sbase); cp_commit();

#pragma unroll 1
    for (int kc = 0; kc < NCHUNK; kc++) {
        cp_wait<1>();        // group kc complete (always exactly 1 newer in flight)
        __syncthreads();     // data visible to all; oldest slot reusable
        if (kc + 2 < NCHUNK) load_chunk(kc + 2, (kc + 2) % NSTAGE, cm, cn, sbase);
        cp_commit();         // empty group on tail keeps wait<1> arithmetic constant

        const uint32_t As = sbase + (kc % NSTAGE) * STAGE_BYTES;
        const uint32_t Bs = As + 16384;
#pragma unroll
        for (int ks = 0; ks < 4; ks++) {
            uint32_t a[2][4];
#pragma unroll
            for (int mi = 0; mi < 2; mi++) {
                uint32_t off = (a_row + mi * 16) * 128 + (ks * 2 + a_sel) * 16;
                off ^= ((off >> 3) & 0x70);
                ldsm4(a[mi][0], a[mi][1], a[mi][2], a[mi][3], As + off);
            }
            uint32_t b[8][2];
#pragma unroll
            for (int nq = 0; nq < 4; nq++) {
                uint32_t off = (b_row + nq * 16) * 128 + (ks * 2 + b_sel) * 16;
                off ^= ((off >> 3) & 0x70);
                ldsm4(b[nq * 2][0], b[nq * 2][1], b[nq * 2 + 1][0], b[nq * 2 + 1][1],
                      Bs + off);
            }
#pragma unroll
            for (int mi = 0; mi < 2; mi++)
#pragma unroll
                for (int nj = 0; nj < 8; nj++)
                    mma16816(acc[mi][nj], a[mi], b[nj]);
        }
    }

    // -------- epilogue: row/col argmax from register fragments --------
#pragma unroll
    for (int mi = 0; mi < 2; mi++)
#pragma unroll
        for (int h = 0; h < 2; h++) {
            unsigned long long best = 0ull;
#pragma unroll
            for (int nj = 0; nj < 8; nj++)
#pragma unroll
                for (int p = 0; p < 2; p++) {
                    float v = acc[mi][nj][h * 2 + p];
                    unsigned col = cn + wn * 64 + nj * 8 + (lane & 3) * 2 + p;
                    best = umax64(best, ((unsigned long long)f2o(v) << 32) | col);
                }
            best = umax64(best, __shfl_xor_sync(0xffffffffu, best, 1));
            best = umax64(best, __shfl_xor_sync(0xffffffffu, best, 2));
            if ((lane & 3) == 0)
                atomicMax(&sRow[wm * 32 + mi * 16 + h * 8 + (lane >> 2)], best);
        }
#pragma unroll
    for (int nj = 0; nj < 8; nj++)
#pragma unroll
        for (int p = 0; p < 2; p++) {
            unsigned long long best = 0ull;
#pragma unroll
            for (int mi = 0; mi < 2; mi++)
#pragma unroll
                for (int h = 0; h < 2; h++) {
                    float v = acc[mi][nj][h * 2 + p];
                    unsigned row = cm + wm * 32 + mi * 16 + h * 8 + (lane >> 2);
                    best = umax64(best, ((unsigned long long)f2o(v) << 32) | row);
                }
            best = umax64(best, __shfl_xor_sync(0xffffffffu, best, 4));
            best = umax64(best, __shfl_xor_sync(0xffffffffu, best, 8));
            best = umax64(best, __shfl_xor_sync(0xffffffffu, best, 16));
            if (lane < 4)
                atomicMax(&sCol[wn * 64 + nj * 8 + (lane & 3) * 2 + p], best);
        }
    __syncthreads();
    if (tid < 128) {
        atomicMax(&g_rbest[cm + tid], sRow[tid]);
        atomicMax(&g_cbest[cn + tid], sCol[tid]);
    }
}

// one warp per (row|col): exact fp32 dot of raw inputs / norms, then entropy term.
// 8 warps per block; each block handles one side only (NR % 8 == 0).
__global__ void refine_entropy_kernel(const float* __restrict__ ex,
                                      const float* __restrict__ ey,
                                      float* __restrict__ out) {
    int w    = (blockIdx.x * blockDim.x + threadIdx.x) >> 5;
    int lane = threadIdx.x & 31;
    int wlocal = (threadIdx.x >> 5);
    int side = (w >= NR);
    const float *va, *vb;
    float nx, ny;
    if (!side) {
        unsigned m = (unsigned)g_rbest[w];
        va = ex + (size_t)w * DIM;  vb = ey + (size_t)m * DIM;
        nx = g_nrm[w];              ny = g_nrm[NR + m];
    } else {
        int c = w - NR;
        unsigned m = (unsigned)g_cbest[c];
        va = ex + (size_t)m * DIM;  vb = ey + (size_t)c * DIM;
        nx = g_nrm[m];              ny = g_nrm[NR + c];
    }
    float s = 0.f;
#pragma unroll
    for (int i = 0; i < 4; i++) {
        int e = (i * 32 + lane) * 4;
        float4 a = *(const float4*)(va + e);
        float4 b = *(const float4*)(vb + e);
        s += a.x * b.x + a.y * b.y + a.z * b.z + a.w * b.w;
    }
#pragma unroll
    for (int off = 16; off; off >>= 1) s += __shfl_xor_sync(0xffffffffu, s, off);

    __shared__ float sacc[8];
    if (lane == 0) {
        float x  = s / (nx * ny);
        float z  = (x - 1.0f) * (1.0f / 0.3f);
        float lp = fmaf(-0.5f, z * z, 0.28503427112126339f);  // -log(.3)-.5log(2pi)
        sacc[wlocal] = -expf(lp) * lp;
    }
    __syncthreads();
    if (threadIdx.x == 0) {
        float t = 0.f;
#pragma unroll
        for (int i = 0; i < 8; i++) t += sacc[i];
        atomicAdd(&out[side], t);
    }
}

extern "C" void kernel_launch(void* const* d_in, const int* in_sizes, int n_in,
                              void* d_out, int out_size) {
    const float* ex = (const float*)d_in[0];
    const float* ey = (const float*)d_in[1];
    float* out = (float*)d_out;

    cudaFuncSetAttribute(gemm_max_kernel, cudaFuncAttributeMaxDynamicSharedMemorySize,
                         SMEM_TOTAL);

    init_kernel<<<(NR + 255) / 256, 256>>>(out, out_size);
    normalize_kernel<<<dim3(NR, 2), 128>>>(ex, ey);
    gemm_max_kernel<<<dim3(NR / TN, NR / TM), NTHREADS, SMEM_TOTAL>>>();
    refine_entropy_kernel<<<(2 * NR) / 8, 256>>>(ex, ey, out);
}